// round 15
// baseline (speedup 1.0000x reference)
#include <cuda_runtime.h>
#include <cuda_fp16.h>
#include <stdint.h>

#define P_PART 16
#define EDIM   512
#define HDIM   512
#define NENT   8192

// ---------------- device scratch (pre-tiled, pre-swizzled) ----------------
__device__ __half g_X16[NENT * EDIM];            // [tile(128)][kc(8)][row(64)][kk(64)], SW128 per 8KB block
__device__ __half g_W0T[P_PART * EDIM * HDIM];   // [p][chunk(8)][n(512)][kk(64)], SW128; 64KB chunks
__device__ __half g_W1T[P_PART * HDIM * HDIM];

// ---------------- helpers ----------------
__device__ __forceinline__ uint32_t h2_bits(__half2 v) {
    return *reinterpret_cast<uint32_t*>(&v);
}
__device__ __forceinline__ __half2 bits_h2(uint32_t v) {
    return *reinterpret_cast<__half2*>(&v);
}
__device__ __forceinline__ uint32_t smem_u32(const void* p) {
    uint32_t a;
    asm("{ .reg .u64 t; cvta.to.shared.u64 t, %1; cvt.u32.u64 %0, t; }" : "=r"(a) : "l"(p));
    return a;
}
__host__ __device__ __forceinline__ uint32_t swz(uint32_t o) { return o ^ ((o >> 3) & 0x70); }

__device__ __forceinline__ void sts32(uint32_t a, uint32_t v) {
    asm volatile("st.shared.b32 [%0], %1;" :: "r"(a), "r"(v) : "memory");
}
__device__ __forceinline__ void ldmatrix_x4(uint32_t& r0, uint32_t& r1, uint32_t& r2,
                                            uint32_t& r3, uint32_t addr) {
    asm volatile("ldmatrix.sync.aligned.m8n8.x4.shared.b16 {%0,%1,%2,%3}, [%4];"
                 : "=r"(r0), "=r"(r1), "=r"(r2), "=r"(r3) : "r"(addr));
}

__device__ __forceinline__ void mbar_init(uint32_t a, uint32_t cnt) {
    asm volatile("mbarrier.init.shared.b64 [%0], %1;" :: "r"(a), "r"(cnt) : "memory");
}
__device__ __forceinline__ void mbar_expect(uint32_t a, uint32_t tx) {
    asm volatile("mbarrier.arrive.expect_tx.shared.b64 _, [%0], %1;" :: "r"(a), "r"(tx) : "memory");
}
__device__ __forceinline__ void mbar_arrive(uint32_t a) {
    asm volatile("mbarrier.arrive.shared.b64 _, [%0];" :: "r"(a) : "memory");
}
__device__ __forceinline__ void mbar_wait(uint32_t a, uint32_t parity) {
    uint32_t done = 0;
    while (!done) {
        asm volatile("{\n\t.reg .pred p;\n\t"
                     "mbarrier.try_wait.parity.acquire.cta.shared::cta.b64 p, [%1], %2, 0x989680;\n\t"
                     "selp.b32 %0,1,0,p;\n\t}"
                     : "=r"(done) : "r"(a), "r"(parity) : "memory");
    }
}
__device__ __forceinline__ void bulk_g2s(uint32_t dst, const void* src, uint32_t bytes,
                                         uint32_t mbar) {
    asm volatile("cp.async.bulk.shared::cluster.global.mbarrier::complete_tx::bytes "
                 "[%0], [%1], %2, [%3];"
                 :: "r"(dst), "l"(src), "r"(bytes), "r"(mbar) : "memory");
}

// fp16-accumulate MMA
__device__ __forceinline__ void mma16816_h(uint32_t* d, const uint32_t* a, const uint32_t* b) {
    asm volatile(
        "mma.sync.aligned.m16n8k16.row.col.f16.f16.f16.f16 "
        "{%0,%1}, {%2,%3,%4,%5}, {%6,%7}, {%0,%1};"
        : "+r"(d[0]), "+r"(d[1])
        : "r"(a[0]), "r"(a[1]), "r"(a[2]), "r"(a[3]), "r"(b[0]), "r"(b[1]));
}

// ---------------- SMEM layout (bytes) ----------------
#define SM_A     0          // 8 blocks x [64 rows x 128B] = 65536 (x, then h)
#define SM_W     65536      // 2 x 65536 weight double buffer ([512 n x 128B] swizzled)
#define SM_B0    196608
#define SM_B1    198656
#define SM_W2    200704
#define SM_LOG   202752     // 64 f32
#define SM_MBAR  203008     // A mbar; full[2]; consumed[2]
#define SMEM_SZ  203072

// ---------------- fused prep kernel ----------------
// blocks [0, 2048): X fp32 -> fp16, 64-row tiles, SW128 8KB blocks (uint4 writes)
// blocks [2048, 6144): W0/W1 -> transposed fp16, 64k x 32n tiles, uint4 writes
__global__ void prep_kernel(const float* __restrict__ X,
                            const float* __restrict__ W0,
                            const float* __restrict__ W1) {
    if (blockIdx.x < 2048) {
        int s = blockIdx.x * 256 + threadIdx.x;
        int n = s >> 6, sr = s & 63;
        const float4* src = reinterpret_cast<const float4*>(X + (size_t)n * 512 + sr * 8);
        float4 v0 = src[0], v1 = src[1];
        __half2 p0 = __floats2half2_rn(v0.x, v0.y);
        __half2 p1 = __floats2half2_rn(v0.z, v0.w);
        __half2 p2 = __floats2half2_rn(v1.x, v1.y);
        __half2 p3 = __floats2half2_rn(v1.z, v1.w);
        uint4 h;
        h.x = h2_bits(p0); h.y = h2_bits(p1); h.z = h2_bits(p2); h.w = h2_bits(p3);
        size_t off = (size_t)(n >> 6) * 65536 + (sr >> 3) * 8192
                   + swz((uint32_t)((n & 63) * 128 + (sr & 7) * 16));
        *reinterpret_cast<uint4*>((char*)g_X16 + off) = h;
        return;
    }
    // W transpose: 64k x 32n tile per block, 16B-coalesced writes
    __shared__ float tile[64][33];
    int bb = blockIdx.x - 2048;          // 0..4095
    int z  = bb & 31;                    // which*16 + p
    int rest = bb >> 5;                  // 0..127
    int which = z >> 4;
    int p = z & 15;
    const float* W = which ? W1 : W0;
    __half* T = which ? g_W1T : g_W0T;
    int c0 = (rest & 15) * 32;           // n base
    int r0 = (rest >> 4) * 64;           // k base (multiple of 64)
    const float* Wp = W + (size_t)p * 262144;
    char* Tp = (char*)T + (size_t)p * 524288;

    // read 64x32 fp32 region: thread (tx=n, ty=k-octet) reads 8 k rows
    int tx = threadIdx.x & 31, ty = threadIdx.x >> 5;
    #pragma unroll
    for (int r = 0; r < 8; r++)
        tile[ty * 8 + r][tx] = Wp[(size_t)(r0 + ty * 8 + r) * 512 + c0 + tx];
    __syncthreads();

    // write: thread t -> n = t>>3, k-octet = t&7; pack 8 halves into uint4
    int n_ = (int)(threadIdx.x >> 3);          // 0..31
    int oct = (int)(threadIdx.x & 7);          // 0..7
    int k8 = oct * 8;
    __half2 q0 = __floats2half2_rn(tile[k8 + 0][n_], tile[k8 + 1][n_]);
    __half2 q1 = __floats2half2_rn(tile[k8 + 2][n_], tile[k8 + 3][n_]);
    __half2 q2 = __floats2half2_rn(tile[k8 + 4][n_], tile[k8 + 5][n_]);
    __half2 q3 = __floats2half2_rn(tile[k8 + 6][n_], tile[k8 + 7][n_]);
    uint4 h;
    h.x = h2_bits(q0); h.y = h2_bits(q1); h.z = h2_bits(q2); h.w = h2_bits(q3);
    size_t off = (size_t)(r0 >> 6) * 65536
               + swz((uint32_t)((c0 + n_) * 128 + k8 * 2));
    *reinterpret_cast<uint4*>(Tp + off) = h;
}

// ---------------- fused MLP kernel: 512 threads, 16 warps, fp16 acc ----------------
__global__ void __launch_bounds__(512, 1)
mlp_kernel(const float* __restrict__ b0, const float* __restrict__ b1,
           const float* __restrict__ W2v, const float* __restrict__ b2,
           float* __restrict__ out) {
    extern __shared__ __align__(1024) char smem[];
    const uint32_t sb = smem_u32(smem);
    const int tid = threadIdx.x, wid = tid >> 5, lid = tid & 31;
    const int p = blockIdx.x;
    const int tile = blockIdx.y;
    const int n0 = tile * 64;

    float* b0s = (float*)(smem + SM_B0);
    float* b1s = (float*)(smem + SM_B1);
    float* w2s = (float*)(smem + SM_W2);
    float* logits = (float*)(smem + SM_LOG);

    const uint32_t mbA = sb + SM_MBAR;
    const uint32_t mbF = sb + SM_MBAR + 8;     // full[b] at +8*b
    const uint32_t mbC = sb + SM_MBAR + 24;    // consumed[b] at +8*b

    if (tid == 0) {
        mbar_init(mbA, 1);
        mbar_init(mbF, 1);     mbar_init(mbF + 8, 1);
        mbar_init(mbC, 16);    mbar_init(mbC + 8, 16);
    }
    __syncthreads();

    const char* w0p = (const char*)g_W0T + (size_t)p * 524288;
    const char* w1p = (const char*)g_W1T + (size_t)p * 524288;

    if (tid == 0) {
        mbar_expect(mbA, 65536);
        bulk_g2s(sb + SM_A, (const char*)g_X16 + (size_t)tile * 65536, 65536, mbA);
        mbar_expect(mbF, 65536);
        bulk_g2s(sb + SM_W, w0p, 65536, mbF);
        mbar_expect(mbF + 8, 65536);
        bulk_g2s(sb + SM_W + 65536, w0p + 65536, 65536, mbF + 8);
    }

    {
        int c = tid;
        b0s[c] = b0[p * 512 + c];
        b1s[c] = b1[p * 512 + c];
        w2s[c] = W2v[p * 512 + c];
    }
    if (tid < 64) logits[tid] = b2[p];
    __syncthreads();

    // fp16x2 accumulators: warp tile 64m x 32n -> acc[4][4][2]
    uint32_t acc[4][4][2];
    #pragma unroll
    for (int mt = 0; mt < 4; mt++)
        #pragma unroll
        for (int nt = 0; nt < 4; nt++) { acc[mt][nt][0] = 0u; acc[mt][nt][1] = 0u; }

    const int arow = lid >> 2;
    const int acol = (lid & 3) * 2;

    const uint32_t a_lrow = (uint32_t)(lid & 15) * 128;
    const uint32_t a_lcol = (uint32_t)(lid >> 4) * 16;
    const int      b_nrow = wid * 32 + ((lid >> 4) << 3) + (lid & 7);
    const uint32_t b_lcol = (uint32_t)((lid >> 3) & 1) * 16;

    mbar_wait(mbA, 0);
    uint32_t phF[2] = {0u, 0u};
    uint32_t phC[2] = {0u, 0u};

    const __half2 hzero = __float2half2_rn(0.f);

    for (int e = 0; e < 16; e++) {
        const int b = e & 1;
        mbar_wait(mbF + b * 8, phF[b]); phF[b] ^= 1;

        const uint32_t ab = sb + SM_A + (e & 7) * 8192;
        const uint32_t wb = sb + SM_W + b * 65536;

        #pragma unroll
        for (int ks = 0; ks < 4; ks++) {
            const uint32_t kb = (uint32_t)ks * 32;
            uint32_t aF[4][4];
            #pragma unroll
            for (int mt = 0; mt < 4; mt++)
                ldmatrix_x4(aF[mt][0], aF[mt][1], aF[mt][2], aF[mt][3],
                            ab + mt * 2048 + swz(a_lrow + kb + a_lcol));
            uint32_t bF[4][2];
            #pragma unroll
            for (int np = 0; np < 2; np++) {
                int nr = b_nrow + np * 16;
                uint32_t addr = wb + (uint32_t)(nr >> 3) * 1024
                              + swz((uint32_t)(nr & 7) * 128 + kb + b_lcol);
                ldmatrix_x4(bF[2 * np][0], bF[2 * np][1],
                            bF[2 * np + 1][0], bF[2 * np + 1][1], addr);
            }
            if (ks == 3 && lid == 0) mbar_arrive(mbC + b * 8);
            #pragma unroll
            for (int mt = 0; mt < 4; mt++)
                #pragma unroll
                for (int nt = 0; nt < 4; nt++)
                    mma16816_h(acc[mt][nt], aF[mt], bF[nt]);
        }

        // producer: recycle buffer b once all 16 warps consumed it
        if (tid == 0 && e + 2 < 16) {
            mbar_wait(mbC + b * 8, phC[b]); phC[b] ^= 1;
            const char* src = (e + 2 < 8) ? (w0p + (size_t)(e + 2) * 65536)
                                          : (w1p + (size_t)(e - 6) * 65536);
            mbar_expect(mbF + b * 8, 65536);
            bulk_g2s(sb + SM_W + b * 65536, src, 65536, mbF + b * 8);
        }

        // ---- layer-0 epilogue: bias+relu in half2, h overwrites x in SMEM ----
        if (e == 7) {
            __syncthreads();
            #pragma unroll
            for (int mt = 0; mt < 4; mt++) {
                #pragma unroll
                for (int nt = 0; nt < 4; nt++) {
                    int row = mt * 16 + arow;
                    int col = wid * 32 + nt * 8 + acol;
                    uint32_t o = (uint32_t)(row * 128 + (col & 63) * 2);
                    uint32_t addr = sb + SM_A + (uint32_t)(col >> 6) * 8192 + swz(o);
                    __half2 bias2 = __floats2half2_rn(b0s[col], b0s[col + 1]);
                    __half2 h01 = __hmax2(__hadd2(bits_h2(acc[mt][nt][0]), bias2), hzero);
                    __half2 h23 = __hmax2(__hadd2(bits_h2(acc[mt][nt][1]), bias2), hzero);
                    sts32(addr, h2_bits(h01));
                    sts32(addr + 1024, h2_bits(h23));
                    acc[mt][nt][0] = 0u; acc[mt][nt][1] = 0u;
                }
            }
            __syncthreads();
        }
    }

    // ---- final epilogue: bias+relu (half2), dot with W2 in fp32, sigmoid ----
    #pragma unroll
    for (int mt = 0; mt < 4; mt++) {
        float s0 = 0.f, s1 = 0.f;
        #pragma unroll
        for (int nt = 0; nt < 4; nt++) {
            int col = wid * 32 + nt * 8 + acol;
            __half2 bias2 = __floats2half2_rn(b1s[col], b1s[col + 1]);
            float2 z01 = __half22float2(__hmax2(__hadd2(bits_h2(acc[mt][nt][0]), bias2), hzero));
            float2 z23 = __half22float2(__hmax2(__hadd2(bits_h2(acc[mt][nt][1]), bias2), hzero));
            float w0c = w2s[col], w1c = w2s[col + 1];
            s0 += z01.x * w0c + z01.y * w1c;
            s1 += z23.x * w0c + z23.y * w1c;
        }
        int row = mt * 16 + arow;
        atomicAdd(&logits[row],     s0);
        atomicAdd(&logits[row + 8], s1);
    }
    __syncthreads();
    if (tid < 64)
        out[(size_t)(n0 + tid) * 16 + p] = 1.f / (1.f + expf(-logits[tid]));
}

// ---------------- launch ----------------
extern "C" void kernel_launch(void* const* d_in, const int* in_sizes, int n_in,
                              void* d_out, int out_size) {
    const float* X  = (const float*)d_in[0];
    const float* W0 = (const float*)d_in[1];
    const float* b0 = (const float*)d_in[2];
    const float* W1 = (const float*)d_in[3];
    const float* b1 = (const float*)d_in[4];
    const float* W2 = (const float*)d_in[5];
    const float* b2 = (const float*)d_in[6];
    float* out = (float*)d_out;

    prep_kernel<<<6144, 256>>>(X, W0, W1);

    cudaFuncSetAttribute(mlp_kernel, cudaFuncAttributeMaxDynamicSharedMemorySize, SMEM_SZ);
    mlp_kernel<<<dim3(P_PART, NENT / 64), 512, SMEM_SZ>>>(b0, b1, W2, b2, out);
}

// round 16
// speedup vs baseline: 1.0853x; 1.0853x over previous
#include <cuda_runtime.h>
#include <cuda_fp16.h>
#include <stdint.h>

#define P_PART 16
#define EDIM   512
#define HDIM   512
#define NENT   8192

// ---------------- device scratch (pre-tiled, pre-swizzled) ----------------
__device__ __half g_X16[NENT * EDIM];            // [tile(128)][kc(8)][row(64)][kk(64)], SW128 per 8KB block
__device__ __half g_W0T[P_PART * EDIM * HDIM];   // [p][chunk(8)][n(512)][kk(64)], SW128; 64KB chunks
__device__ __half g_W1T[P_PART * HDIM * HDIM];

// ---------------- helpers ----------------
__device__ __forceinline__ uint32_t h2_bits(__half2 v) {
    return *reinterpret_cast<uint32_t*>(&v);
}
__device__ __forceinline__ __half2 bits_h2(uint32_t v) {
    return *reinterpret_cast<__half2*>(&v);
}
__device__ __forceinline__ uint32_t smem_u32(const void* p) {
    uint32_t a;
    asm("{ .reg .u64 t; cvta.to.shared.u64 t, %1; cvt.u32.u64 %0, t; }" : "=r"(a) : "l"(p));
    return a;
}
__host__ __device__ __forceinline__ uint32_t swz(uint32_t o) { return o ^ ((o >> 3) & 0x70); }

__device__ __forceinline__ void sts32(uint32_t a, uint32_t v) {
    asm volatile("st.shared.b32 [%0], %1;" :: "r"(a), "r"(v) : "memory");
}
__device__ __forceinline__ void ldmatrix_x4(uint32_t& r0, uint32_t& r1, uint32_t& r2,
                                            uint32_t& r3, uint32_t addr) {
    asm volatile("ldmatrix.sync.aligned.m8n8.x4.shared.b16 {%0,%1,%2,%3}, [%4];"
                 : "=r"(r0), "=r"(r1), "=r"(r2), "=r"(r3) : "r"(addr));
}

__device__ __forceinline__ void mbar_init(uint32_t a, uint32_t cnt) {
    asm volatile("mbarrier.init.shared.b64 [%0], %1;" :: "r"(a), "r"(cnt) : "memory");
}
__device__ __forceinline__ void mbar_expect(uint32_t a, uint32_t tx) {
    asm volatile("mbarrier.arrive.expect_tx.shared.b64 _, [%0], %1;" :: "r"(a), "r"(tx) : "memory");
}
__device__ __forceinline__ void mbar_arrive(uint32_t a) {
    asm volatile("mbarrier.arrive.shared.b64 _, [%0];" :: "r"(a) : "memory");
}
__device__ __forceinline__ void mbar_wait(uint32_t a, uint32_t parity) {
    uint32_t done = 0;
    while (!done) {
        asm volatile("{\n\t.reg .pred p;\n\t"
                     "mbarrier.try_wait.parity.acquire.cta.shared::cta.b64 p, [%1], %2, 0x989680;\n\t"
                     "selp.b32 %0,1,0,p;\n\t}"
                     : "=r"(done) : "r"(a), "r"(parity) : "memory");
    }
}
__device__ __forceinline__ void bulk_g2s(uint32_t dst, const void* src, uint32_t bytes,
                                         uint32_t mbar) {
    asm volatile("cp.async.bulk.shared::cluster.global.mbarrier::complete_tx::bytes "
                 "[%0], [%1], %2, [%3];"
                 :: "r"(dst), "l"(src), "r"(bytes), "r"(mbar) : "memory");
}

// fp16-accumulate MMA: D(f16x2 x2) = A*B + D
__device__ __forceinline__ void mma16816_h(uint32_t* d, const uint32_t* a, const uint32_t* b) {
    asm volatile(
        "mma.sync.aligned.m16n8k16.row.col.f16.f16.f16.f16 "
        "{%0,%1}, {%2,%3,%4,%5}, {%6,%7}, {%0,%1};"
        : "+r"(d[0]), "+r"(d[1])
        : "r"(a[0]), "r"(a[1]), "r"(a[2]), "r"(a[3]), "r"(b[0]), "r"(b[1]));
}

// ---------------- SMEM layout (bytes) ----------------
#define SM_A     0          // 8 blocks x [64 rows x 128B] = 65536 (x, then h)
#define SM_W     65536      // 2 x 65536 weight double buffer ([512 n x 128B] swizzled)
#define SM_B0    196608
#define SM_B1    198656
#define SM_W2    200704
#define SM_LOG   202752     // 64 f32
#define SM_MBAR  203008     // A mbar; full[2]; consumed[2]
#define SMEM_SZ  203072

// ---------------- fused prep kernel (coalesced 16B writes) ----------------
// blocks [0, 2048): X fp32 -> fp16, 64-row tiles, SW128 8KB blocks (uint4 writes)
// blocks [2048, 6144): W0/W1 -> transposed fp16, 64k x 32n tiles, uint4 writes
__global__ void prep_kernel(const float* __restrict__ X,
                            const float* __restrict__ W0,
                            const float* __restrict__ W1) {
    if (blockIdx.x < 2048) {
        int s = blockIdx.x * 256 + threadIdx.x;
        int n = s >> 6, sr = s & 63;
        const float4* src = reinterpret_cast<const float4*>(X + (size_t)n * 512 + sr * 8);
        float4 v0 = src[0], v1 = src[1];
        __half2 p0 = __floats2half2_rn(v0.x, v0.y);
        __half2 p1 = __floats2half2_rn(v0.z, v0.w);
        __half2 p2 = __floats2half2_rn(v1.x, v1.y);
        __half2 p3 = __floats2half2_rn(v1.z, v1.w);
        uint4 h;
        h.x = h2_bits(p0); h.y = h2_bits(p1); h.z = h2_bits(p2); h.w = h2_bits(p3);
        size_t off = (size_t)(n >> 6) * 65536 + (sr >> 3) * 8192
                   + swz((uint32_t)((n & 63) * 128 + (sr & 7) * 16));
        *reinterpret_cast<uint4*>((char*)g_X16 + off) = h;
        return;
    }
    // W transpose: 64k x 32n tile per block, 16B-coalesced writes
    __shared__ float tile[64][33];
    int bb = blockIdx.x - 2048;          // 0..4095
    int z  = bb & 31;                    // which*16 + p
    int rest = bb >> 5;                  // 0..127
    int which = z >> 4;
    int p = z & 15;
    const float* W = which ? W1 : W0;
    __half* T = which ? g_W1T : g_W0T;
    int c0 = (rest & 15) * 32;           // n base
    int r0 = (rest >> 4) * 64;           // k base (multiple of 64)
    const float* Wp = W + (size_t)p * 262144;
    char* Tp = (char*)T + (size_t)p * 524288;

    int tx = threadIdx.x & 31, ty = threadIdx.x >> 5;
    #pragma unroll
    for (int r = 0; r < 8; r++)
        tile[ty * 8 + r][tx] = Wp[(size_t)(r0 + ty * 8 + r) * 512 + c0 + tx];
    __syncthreads();

    int n_ = (int)(threadIdx.x >> 3);          // 0..31
    int oct = (int)(threadIdx.x & 7);          // 0..7
    int k8 = oct * 8;
    __half2 q0 = __floats2half2_rn(tile[k8 + 0][n_], tile[k8 + 1][n_]);
    __half2 q1 = __floats2half2_rn(tile[k8 + 2][n_], tile[k8 + 3][n_]);
    __half2 q2 = __floats2half2_rn(tile[k8 + 4][n_], tile[k8 + 5][n_]);
    __half2 q3 = __floats2half2_rn(tile[k8 + 6][n_], tile[k8 + 7][n_]);
    uint4 h;
    h.x = h2_bits(q0); h.y = h2_bits(q1); h.z = h2_bits(q2); h.w = h2_bits(q3);
    size_t off = (size_t)(r0 >> 6) * 65536
               + swz((uint32_t)((c0 + n_) * 128 + k8 * 2));
    *reinterpret_cast<uint4*>(Tp + off) = h;
}

// ---------------- fused MLP kernel (R14: 256 thr, 8 warps, fp16 acc) ----------------
__global__ void __launch_bounds__(256, 1)
mlp_kernel(const float* __restrict__ b0, const float* __restrict__ b1,
           const float* __restrict__ W2v, const float* __restrict__ b2,
           float* __restrict__ out) {
    extern __shared__ __align__(1024) char smem[];
    const uint32_t sb = smem_u32(smem);
    const int tid = threadIdx.x, wid = tid >> 5, lid = tid & 31;
    const int p = blockIdx.x;
    const int tile = blockIdx.y;
    const int n0 = tile * 64;

    float* b0s = (float*)(smem + SM_B0);
    float* b1s = (float*)(smem + SM_B1);
    float* w2s = (float*)(smem + SM_W2);
    float* logits = (float*)(smem + SM_LOG);

    const uint32_t mbA = sb + SM_MBAR;
    const uint32_t mbF = sb + SM_MBAR + 8;     // full[b] at +8*b
    const uint32_t mbC = sb + SM_MBAR + 24;    // consumed[b] at +8*b

    if (tid == 0) {
        mbar_init(mbA, 1);
        mbar_init(mbF, 1);     mbar_init(mbF + 8, 1);
        mbar_init(mbC, 8);     mbar_init(mbC + 8, 8);
    }
    __syncthreads();

    const char* w0p = (const char*)g_W0T + (size_t)p * 524288;
    const char* w1p = (const char*)g_W1T + (size_t)p * 524288;

    if (tid == 0) {
        mbar_expect(mbA, 65536);
        bulk_g2s(sb + SM_A, (const char*)g_X16 + (size_t)tile * 65536, 65536, mbA);
        mbar_expect(mbF, 65536);
        bulk_g2s(sb + SM_W, w0p, 65536, mbF);
        mbar_expect(mbF + 8, 65536);
        bulk_g2s(sb + SM_W + 65536, w0p + 65536, 65536, mbF + 8);
    }

    for (int c = tid; c < 512; c += 256) {
        b0s[c] = b0[p * 512 + c];
        b1s[c] = b1[p * 512 + c];
        w2s[c] = W2v[p * 512 + c];
    }
    if (tid < 64) logits[tid] = b2[p];
    __syncthreads();

    // fp16x2 accumulators: [mt][nt][half-pair]; 0 bits == (+0,+0)
    uint32_t acc[4][8][2];
    #pragma unroll
    for (int mt = 0; mt < 4; mt++)
        #pragma unroll
        for (int nt = 0; nt < 8; nt++) { acc[mt][nt][0] = 0u; acc[mt][nt][1] = 0u; }

    const int arow = lid >> 2;
    const int acol = (lid & 3) * 2;

    const uint32_t a_lrow = (uint32_t)(lid & 15) * 128;
    const uint32_t a_lcol = (uint32_t)(lid >> 4) * 16;
    const int      b_nrow = wid * 64 + ((lid >> 4) << 3) + (lid & 7);
    const uint32_t b_lcol = (uint32_t)((lid >> 3) & 1) * 16;

    mbar_wait(mbA, 0);
    uint32_t phF[2] = {0u, 0u};
    uint32_t phC[2] = {0u, 0u};

    const __half2 hzero = __float2half2_rn(0.f);

    for (int e = 0; e < 16; e++) {
        const int b = e & 1;
        mbar_wait(mbF + b * 8, phF[b]); phF[b] ^= 1;

        const uint32_t ab = sb + SM_A + (e & 7) * 8192;
        const uint32_t wb = sb + SM_W + b * 65536;

        #pragma unroll
        for (int ks = 0; ks < 4; ks++) {
            const uint32_t kb = (uint32_t)ks * 32;
            uint32_t aF[4][4];
            #pragma unroll
            for (int mt = 0; mt < 4; mt++)
                ldmatrix_x4(aF[mt][0], aF[mt][1], aF[mt][2], aF[mt][3],
                            ab + mt * 2048 + swz(a_lrow + kb + a_lcol));
            uint32_t bF[8][2];
            #pragma unroll
            for (int np = 0; np < 4; np++) {
                int nr = b_nrow + np * 16;
                uint32_t addr = wb + (uint32_t)(nr >> 3) * 1024
                              + swz((uint32_t)(nr & 7) * 128 + kb + b_lcol);
                ldmatrix_x4(bF[2 * np][0], bF[2 * np][1],
                            bF[2 * np + 1][0], bF[2 * np + 1][1], addr);
            }
            if (ks == 3 && lid == 0) mbar_arrive(mbC + b * 8);
            #pragma unroll
            for (int mt = 0; mt < 4; mt++)
                #pragma unroll
                for (int nt = 0; nt < 8; nt++)
                    mma16816_h(acc[mt][nt], aF[mt], bF[nt]);
        }

        // producer: recycle buffer b once all 8 warps consumed it
        if (tid == 0 && e + 2 < 16) {
            mbar_wait(mbC + b * 8, phC[b]); phC[b] ^= 1;
            const char* src = (e + 2 < 8) ? (w0p + (size_t)(e + 2) * 65536)
                                          : (w1p + (size_t)(e - 6) * 65536);
            mbar_expect(mbF + b * 8, 65536);
            bulk_g2s(sb + SM_W + b * 65536, src, 65536, mbF + b * 8);
        }

        // ---- layer-0 epilogue: bias+relu in half2, h overwrites x in SMEM ----
        if (e == 7) {
            __syncthreads();
            #pragma unroll
            for (int mt = 0; mt < 4; mt++) {
                #pragma unroll
                for (int nt = 0; nt < 8; nt++) {
                    int row = mt * 16 + arow;
                    int col = wid * 64 + nt * 8 + acol;
                    uint32_t o = (uint32_t)(row * 128 + (col & 63) * 2);
                    uint32_t addr = sb + SM_A + (uint32_t)(col >> 6) * 8192 + swz(o);
                    __half2 bias2 = __floats2half2_rn(b0s[col], b0s[col + 1]);
                    __half2 h01 = __hmax2(__hadd2(bits_h2(acc[mt][nt][0]), bias2), hzero);
                    __half2 h23 = __hmax2(__hadd2(bits_h2(acc[mt][nt][1]), bias2), hzero);
                    sts32(addr, h2_bits(h01));
                    sts32(addr + 1024, h2_bits(h23));
                    acc[mt][nt][0] = 0u; acc[mt][nt][1] = 0u;
                }
            }
            __syncthreads();
        }
    }

    // ---- final epilogue: bias+relu (half2), dot with W2 in fp32, sigmoid ----
    #pragma unroll
    for (int mt = 0; mt < 4; mt++) {
        float s0 = 0.f, s1 = 0.f;
        #pragma unroll
        for (int nt = 0; nt < 8; nt++) {
            int col = wid * 64 + nt * 8 + acol;
            __half2 bias2 = __floats2half2_rn(b1s[col], b1s[col + 1]);
            float2 z01 = __half22float2(__hmax2(__hadd2(bits_h2(acc[mt][nt][0]), bias2), hzero));
            float2 z23 = __half22float2(__hmax2(__hadd2(bits_h2(acc[mt][nt][1]), bias2), hzero));
            float w0c = w2s[col], w1c = w2s[col + 1];
            s0 += z01.x * w0c + z01.y * w1c;
            s1 += z23.x * w0c + z23.y * w1c;
        }
        int row = mt * 16 + arow;
        atomicAdd(&logits[row],     s0);
        atomicAdd(&logits[row + 8], s1);
    }
    __syncthreads();
    if (tid < 64)
        out[(size_t)(n0 + tid) * 16 + p] = 1.f / (1.f + expf(-logits[tid]));
}

// ---------------- launch ----------------
extern "C" void kernel_launch(void* const* d_in, const int* in_sizes, int n_in,
                              void* d_out, int out_size) {
    const float* X  = (const float*)d_in[0];
    const float* W0 = (const float*)d_in[1];
    const float* b0 = (const float*)d_in[2];
    const float* W1 = (const float*)d_in[3];
    const float* b1 = (const float*)d_in[4];
    const float* W2 = (const float*)d_in[5];
    const float* b2 = (const float*)d_in[6];
    float* out = (float*)d_out;

    prep_kernel<<<6144, 256>>>(X, W0, W1);

    cudaFuncSetAttribute(mlp_kernel, cudaFuncAttributeMaxDynamicSharedMemorySize, SMEM_SZ);
    mlp_kernel<<<dim3(P_PART, NENT / 64), 256, SMEM_SZ>>>(b0, b1, W2, b2, out);
}